// round 11
// baseline (speedup 1.0000x reference)
#include <cuda_runtime.h>
#include <cuda_bf16.h>
#include <math_constants.h>

#define NPARTS 24
#define MAXB   64
#define MAXN   16384
#define MAXC   128
#define XSLOTS 16    // xyz blocks per batch (2 warp-partials each -> 32 slots/batch)
#define NH     2     // n-halves per channel-pair in feat path

// __device__ scratch (allocation-free per harness rules)
__device__ unsigned int g_labels8[(MAXB * MAXN) / 4];             // u8-packed labels, 1 MB
__device__ float  g_partf[MAXB * XSLOTS * 2 * NPARTS * 4];        // [warp-slot][k][comp] xyz partials
__device__ float2 g_feat[MAXB * (MAXC/2) * NH * NPARTS * 2];      // per-warp {sum,max} partials

// ---------------------------------------------------------------------------
// Kernel 1: pack labels to u8. Only dependency of the feat path, so it must
// be FAST: 4 independent grid-strided int4 loads per thread => ~28 KB DRAM
// bytes in flight per SM (> the ~12.7 KB BW*latency product), instead of the
// R10 version's ~0.9 KB that left it latency-bound at 5.6us.
// ---------------------------------------------------------------------------
__global__ __launch_bounds__(256) void pack_kernel(
    const int* __restrict__ labels, int BN4)
{
    const int T = gridDim.x * blockDim.x;             // BN4 / 4 threads
    const int t = blockIdx.x * blockDim.x + threadIdx.x;
    const int4* __restrict__ l4 = (const int4*)labels;

    int4 v[4];
    #pragma unroll
    for (int j = 0; j < 4; ++j) {
        const int i = t + j * T;
        if (i < BN4) v[j] = l4[i];                    // 4 independent loads
    }
    #pragma unroll
    for (int j = 0; j < 4; ++j) {
        const int i = t + j * T;
        if (i < BN4)
            g_labels8[i] = (unsigned)v[j].x | ((unsigned)v[j].y << 8) |
                           ((unsigned)v[j].z << 16) | ((unsigned)v[j].w << 24);
    }
}

// ---------------------------------------------------------------------------
// Kernel 2: fused (UNCHANGED from R10 — proven). 64-thread blocks, 12 KB smem.
//   blocks [0, B*XSLOTS)   : xyz partial sums (component scheme) — wave 1,
//                            hidden under the feature stream.
//   blocks [B*XSLOTS, ...) : exact R7 feat path (pair scheme, u8 labels,
//                            depth-2 pipeline).
// ---------------------------------------------------------------------------
#define RMW1(f, k) do {                               \
    float2 _v = ap[(k) * 32];                         \
    _v.x += (f); _v.y = fmaxf(_v.y, (f));             \
    ap[(k) * 32] = _v;                                \
} while (0)

#define RMW4(f, q) do {                               \
    RMW1((f).x, (q) & 255);                           \
    RMW1((f).y, ((q) >> 8) & 255);                    \
    RMW1((f).z, ((q) >> 16) & 255);                   \
    RMW1((f).w, (q) >> 24);                           \
} while (0)

__global__ __launch_bounds__(64) void fused_kernel(
    const float* __restrict__ features, const float* __restrict__ xyz,
    const int* __restrict__ labels, int N, int C, int B)
{
    const int w    = threadIdx.x >> 5;
    const int lane = threadIdx.x & 31;

    __shared__ float4 acc4[2][NPARTS][16];            // 12 KB (both paths)
    const int XYZB = B * XSLOTS;

    if (blockIdx.x < XYZB) {
        // ---------------- xyz path (component scheme) ----------------
        const int g = lane >> 2;
        const int c = lane & 3;
        float* accf = (float*)&acc4[w][0][0];         // [k*64 + lane]
        #pragma unroll
        for (int k = 0; k < NPARTS; ++k)
            accf[k * 64 + lane] = 0.f;
        __syncwarp();

        const int b     = blockIdx.x / XSLOTS;
        const int s     = blockIdx.x % XSLOTS;
        const int chunk = N / XSLOTS;                 // 1024 points per block
        const int base  = b * N + s * chunk + w * (chunk >> 1);
        const int iters = chunk >> 4;                 // 8 points per warp-iter

        // depth-2 prefetch
        int   pt   = base + g;
        int   lab0 = labels[pt];
        float v0   = (c < 3) ? xyz[3 * pt + c] : 1.0f;

        for (int i = 0; i < iters - 1; ++i) {
            const int ptn  = base + (i + 1) * 8 + g;
            const int   lab1 = labels[ptn];
            const float v1   = (c < 3) ? xyz[3 * ptn + c] : 1.0f;
            accf[lab0 * 64 + lane] += v0;
            lab0 = lab1; v0 = v1;
        }
        accf[lab0 * 64 + lane] += v0;
        __syncwarp();

        const int slot = blockIdx.x * 2 + w;          // 32 slots per batch
        for (int k = 0; k < NPARTS; ++k) {
            float v = accf[k * 64 + lane];
            v += __shfl_xor_sync(0xFFFFFFFFu, v, 4);
            v += __shfl_xor_sync(0xFFFFFFFFu, v, 8);
            v += __shfl_xor_sync(0xFFFFFFFFu, v, 16);
            if (lane < 4)
                g_partf[((size_t)slot * NPARTS + k) * 4 + c] = v;
        }
        return;
    }

    // ---------------- feat path (exact R7) ----------------
    const int pair = lane >> 1;
    const int odd  = lane & 1;
    const int tasks_per_b = (C / 2) * NH;             // 128
    const int gwid = (blockIdx.x - XYZB) * 2 + w;
    const int b  = gwid / tasks_per_b;
    const int r  = gwid % tasks_per_b;
    const int cp = r >> 1;                            // channel pair
    const int h  = r & 1;                             // n-half

    float2* ap = (float2*)((char*)(&acc4[w][0][0]) + pair * 16 + odd * 8);
    #pragma unroll
    for (int k = 0; k < NPARTS; ++k)
        ap[k * 32] = make_float2(0.f, -CUDART_INF_F);
    __syncwarp();

    const int c = cp * 2 + odd;
    const float4* __restrict__ fr =
        (const float4*)features + ((size_t)(b * C + c) * (N >> 2));
    const unsigned* __restrict__ lr = g_labels8 + (((size_t)b * N) >> 2);

    const int half4 = N >> 3;                         // float4 words per half
    const int base  = h * half4;
    const int iters = half4 >> 4;                     // 16 words per warp-iter

    // depth-2 pipeline (R7-proven)
    float4   f0 = __ldcs(&fr[base + pair]);
    unsigned q0 = lr[base + pair];
    float4   f1 = __ldcs(&fr[base + 16 + pair]);
    unsigned q1 = lr[base + 16 + pair];

    for (int i = 0; i < iters - 2; ++i) {
        const int nb = base + (i + 2) * 16 + pair;
        const float4   f2 = __ldcs(&fr[nb]);
        const unsigned q2 = lr[nb];
        RMW4(f0, q0);
        f0 = f1; q0 = q1; f1 = f2; q1 = q2;
    }
    RMW4(f0, q0);
    RMW4(f1, q1);
    __syncwarp();

    for (int k = 0; k < NPARTS; ++k) {
        float2 v = ap[k * 32];
        #pragma unroll
        for (int off = 2; off < 32; off <<= 1) {
            v.x += __shfl_xor_sync(0xFFFFFFFFu, v.x, off);
            v.y = fmaxf(v.y, __shfl_xor_sync(0xFFFFFFFFu, v.y, off));
        }
        if (lane < 2)   // lane0 = chan A total, lane1 = chan B total
            g_feat[(size_t)gwid * (2 * NPARTS) + 2 * k + odd] = v;
    }
}

// ---------------------------------------------------------------------------
// Kernel 3: merge (UNCHANGED from R10) — one WARP per (b,k).
// ---------------------------------------------------------------------------
__global__ __launch_bounds__(256) void merge_kernel(
    float* __restrict__ out, int C, int B)
{
    const int warp = (blockIdx.x * blockDim.x + threadIdx.x) >> 5;
    const int lane = threadIdx.x & 31;
    if (warp >= B * NPARTS) return;
    const int b = warp / NPARTS, k = warp % NPARTS;

    const int slot = b * (XSLOTS * 2) + lane;         // exactly 32 slots
    float4 v = *(const float4*)&g_partf[((size_t)slot * NPARTS + k) * 4];
    #pragma unroll
    for (int off = 16; off; off >>= 1) {
        v.x += __shfl_xor_sync(0xFFFFFFFFu, v.x, off);
        v.y += __shfl_xor_sync(0xFFFFFFFFu, v.y, off);
        v.z += __shfl_xor_sync(0xFFFFFFFFu, v.z, off);
        v.w += __shfl_xor_sync(0xFFFFFFFFu, v.w, off);
    }
    const float denom = fmaxf(v.w, 1.f);

    const int outd = 3 + 2 * C;
    float* o = out + (size_t)(b * NPARTS + k) * outd;
    if (lane == 0) {
        o[0] = v.x / denom;
        o[1] = v.y / denom;
        o[2] = v.z / denom;
    }

    for (int cp = lane; cp < C / 2; cp += 32) {
        const int g0 = (b * (C / 2) + cp) * NH;
        const float2 a0 = g_feat[(size_t)(g0 + 0) * (2 * NPARTS) + 2 * k + 0];
        const float2 a1 = g_feat[(size_t)(g0 + 1) * (2 * NPARTS) + 2 * k + 0];
        const float2 b0 = g_feat[(size_t)(g0 + 0) * (2 * NPARTS) + 2 * k + 1];
        const float2 b1 = g_feat[(size_t)(g0 + 1) * (2 * NPARTS) + 2 * k + 1];

        const float meanA = (a0.x + a1.x) / denom;
        const float meanB = (b0.x + b1.x) / denom;
        const float maxA  = fmaxf(a0.y, a1.y);
        const float maxB  = fmaxf(b0.y, b1.y);

        const int c0 = cp * 2;
        o[3 + c0]         = meanA;
        o[3 + c0 + 1]     = meanB;
        o[3 + C + c0]     = fmaxf(maxA - meanA, 0.f);  // empty seg: -inf -> 0
        o[3 + C + c0 + 1] = fmaxf(maxB - meanB, 0.f);
    }
}

extern "C" void kernel_launch(void* const* d_in, const int* in_sizes, int n_in,
                              void* d_out, int out_size)
{
    const float* xyz      = (const float*)d_in[0];
    const float* features = (const float*)d_in[1];
    const int*   labels   = (const int*)d_in[2];
    float* out = (float*)d_out;

    const long long BN = in_sizes[2];                  // B*N
    const int C = (int)((long long)in_sizes[1] / BN);  // 128
    const int outd = 3 + 2 * C;                        // 259
    const int B = out_size / (NPARTS * outd);          // 64
    const int N = (int)(BN / B);                       // 16384

    const int BN4 = (int)(BN >> 2);
    const int pack_threads = (BN4 + 3) / 4;            // 4 words per thread
    pack_kernel<<<(pack_threads + 255) / 256, 256>>>(labels, BN4);

    const int xyz_blocks  = B * XSLOTS;                // 1024
    const int feat_blocks = B * (C / 2) * NH / 2;      // 4096
    fused_kernel<<<xyz_blocks + feat_blocks, 64>>>(features, xyz, labels, N, C, B);

    merge_kernel<<<(B * NPARTS * 32 + 255) / 256, 256>>>(out, C, B);
}